// round 6
// baseline (speedup 1.0000x reference)
#include <cuda_runtime.h>
#include <cstdint>

typedef unsigned int u32;
typedef unsigned long long u64;

#define F       128
#define NI      31
#define NL      32
#define TMAX    20
#define NGROUP  5            // 5 groups x 4 trees (128 node-cols per group)
#define TILE_M  64
#define NTHREADS 256

// ---- SMEM layout (float indices) ----
#define STX    132           // X row stride: banks (4g+t4) distinct -> conflict-free LDS.32
#define STWS   136           // W row stride: float2-slot stride 68 == 4 mod 16 -> conflict-free LDS.64
#define STL    129           // logits row stride: epilogue loads conflict-free (bank = row+c)
#define X_F    0                          // 64*132  = 8448
#define W0_F   8448                       // 128*136 = 17408
#define W1_F   25856                      // 17408
#define L_F    43264                      // 64*129  = 8256
#define SP_F   51520                      // 512
#define SMEM_FLOATS 52032
#define SMEM_BYTES  (SMEM_FLOATS * 4)     // 208128

// __device__ scratch (allocation-free)
__device__ float g_W[NGROUP * 128 * F];  // tf32-rounded masked weights, k pair-permuted
__device__ float g_sc[TMAX * 64];        // softmax(tree_w)[t] * softmax(leaf_logits)[t,l,:]

__constant__ float c_bs[TMAX * NI];      // split bias
__constant__ float c_sc[TMAX * 64];      // leaf/class scales

// ---------------- helpers ----------------
__device__ __forceinline__ u32 smem_u32(const void* p) {
    u32 a;
    asm("{ .reg .u64 t; cvta.to.shared.u64 t, %1; cvt.u32.u64 %0, t; }" : "=r"(a) : "l"(p));
    return a;
}
__device__ __forceinline__ void cpa16(u32 dst, const void* src) {
    asm volatile("cp.async.cg.shared.global [%0], [%1], 16;" :: "r"(dst), "l"(src) : "memory");
}
#define CP_COMMIT() asm volatile("cp.async.commit_group;" ::: "memory")
template<int N> __device__ __forceinline__ void cp_wait() {
    asm volatile("cp.async.wait_group %0;" :: "n"(N) : "memory");
}
__device__ __forceinline__ void lds_v2(u32& a, u32& b, u32 addr) {
    asm volatile("ld.shared.v2.u32 {%0,%1}, [%2];" : "=r"(a), "=r"(b) : "r"(addr));
}

#define MMA_TF32(c, a, b0, b1) \
    asm volatile("mma.sync.aligned.m16n8k8.row.col.f32.tf32.tf32.f32 " \
        "{%0,%1,%2,%3}, {%4,%5,%6,%7}, {%8,%9}, {%0,%1,%2,%3};" \
        : "+f"((c)[0]), "+f"((c)[1]), "+f"((c)[2]), "+f"((c)[3]) \
        : "r"((a)[0]), "r"((a)[1]), "r"((a)[2]), "r"((a)[3]), "r"(b0), "r"(b1))

// ---------------- prologue ----------------
// g_W layout: [g][nrow 0..127][slot], slot = pair-permuted k so the B fragment
// (k = ko+t4, ko+t4+4) sits in adjacent floats -> one LDS.64.
__global__ void prep(const float* __restrict__ sw, const float* __restrict__ fm,
                     const float* __restrict__ ll, const float* __restrict__ tw, int T) {
    int idx = blockIdx.x * 256 + threadIdx.x;
    const int total = NGROUP * 128 * F;   // 81920
    if (idx < total) {
        int k    = idx & 127;
        int nrow = (idx >> 7) & 127;
        int g    = idx >> 14;
        int t    = g * 4 + (nrow >> 5);
        int n    = nrow & 31;
        float v = 0.f;
        if (t < T && n < NI) v = sw[(t * NI + n) * F + k] * fm[t * F + k];
        u32 o;
        asm("cvt.rna.tf32.f32 %0, %1;" : "=r"(o) : "f"(v));
        int slot = (k & ~7) + ((k & 3) << 1) + ((k >> 2) & 1);
        ((u32*)g_W)[(idx & ~127) + slot] = o;
    }
    if (idx < TMAX * NL) {
        int t = idx >> 5, l = idx & 31;
        float w0 = 0.f, w1 = 0.f;
        if (t < T) {
            float m = -1e30f;
            for (int k = 0; k < T; k++) m = fmaxf(m, tw[k]);
            float den = 0.f;
            for (int k = 0; k < T; k++) den += expf(tw[k] - m);
            float w = expf(tw[t] - m) / den;
            float a = ll[(t * NL + l) * 2 + 0];
            float b = ll[(t * NL + l) * 2 + 1];
            float mm = fmaxf(a, b);
            float ea = expf(a - mm), eb = expf(b - mm);
            float inv = w / (ea + eb);
            w0 = ea * inv; w1 = eb * inv;
        }
        g_sc[(idx >> 5) * 64 + (idx & 31) * 2 + 0] = w0;
        g_sc[(idx >> 5) * 64 + (idx & 31) * 2 + 1] = w1;
    }
}

// ---------------- main fused kernel ----------------
// TILE_M=64, 256 threads = 8 warps as 2(M)x4(N). Per group-body:
//   prefetch W(g+1) | [epilogue(g-1) || GEMM(g)] | STS logits(g)
// Epilogue: 1 (row,tree) per thread; bias/scales from __constant__.
__global__ void __launch_bounds__(NTHREADS, 1) forest_mma(
    const float* __restrict__ x, float* __restrict__ out, int B)
{
    extern __shared__ char smem[];
    float* smf = (float*)smem;
    const u32 sbase = smem_u32(smem);
    const int tid  = threadIdx.x;
    const int wid  = tid >> 5;
    const int lane = tid & 31;
    const int gid  = lane >> 2;
    const int tid4 = lane & 3;
    const int warp_m = wid & 1;      // 2 M-groups of 32 rows
    const int warp_n = wid >> 1;     // 4 N-groups of 32 cols
    const int m0 = blockIdx.x * TILE_M;

    // ---- stage X tile + W group 0 (one commit group) ----
    for (int i = tid; i < 2048; i += NTHREADS) {     // 64 rows x 32 chunks
        int row = i >> 5, c = i & 31;
        cpa16(sbase + (u32)(X_F + row * STX) * 4 + c * 16, x + (size_t)(m0 + row) * F + c * 4);
    }
    for (int i = tid; i < 4096; i += NTHREADS) {     // 128 rows x 32 chunks
        int row = i >> 5, c = i & 31;
        cpa16(sbase + (u32)(W0_F + row * STWS) * 4 + c * 16, g_W + row * F + c * 4);
    }
    CP_COMMIT();

    const int erow = tid & 63;       // epilogue row
    const int etl  = tid >> 6;       // epilogue tree-in-group (0..3)
    float o0 = 0.f, o1 = 0.f;

    const u32 Xa_base = sbase + (u32)(X_F + (warp_m * 32 + gid) * STX + tid4) * 4;
    const u32 Wb_rel  = (u32)((warp_n * 32 + gid) * STWS + tid4 * 2) * 4;
    const u32 Lr_base = sbase + (u32)(L_F + erow * STL + etl * 32) * 4;

    #pragma unroll 1
    for (int g = 0; g < NGROUP; g++) {
        const int wf = (g & 1) ? W1_F : W0_F;

        __syncthreads();   // GEMM(g-1) done reading other W buf; L(g-1) fully stored
        if (g < NGROUP - 1) {
            const int wfn = (g & 1) ? W0_F : W1_F;
            const float* src = g_W + (size_t)(g + 1) * 128 * F;
            for (int i = tid; i < 4096; i += NTHREADS) {
                int row = i >> 5, c = i & 31;
                cpa16(sbase + (u32)(wfn + row * STWS) * 4 + c * 16, src + row * F + c * 4);
            }
            CP_COMMIT();
            cp_wait<1>();
        } else {
            cp_wait<0>();
        }
        __syncthreads();   // W(g) visible to all warps; logits(g-1) visible

        float acc[2][4][4];
        #pragma unroll
        for (int mt = 0; mt < 2; mt++)
            #pragma unroll
            for (int nt = 0; nt < 4; nt++)
                #pragma unroll
                for (int q = 0; q < 4; q++) acc[mt][nt][q] = 0.f;

        // ======== epilogue(g-1)  ||  GEMM(g) — one scheduling region ========
        if (g > 0) {
            const int t = (g - 1) * 4 + etl;
            const float* Lr = (const float*)(size_t)0;  // (addr arithmetic below)
            const float* bs = c_bs + t * NI;
            const float* sc = c_sc + t * 64;
            float s[NI];
            #pragma unroll
            for (int n = 0; n < NI; n++) {
                float lv;
                asm volatile("ld.shared.f32 %0, [%1];" : "=f"(lv) : "r"(Lr_base + n * 4));
                float lg = lv + bs[n];
                float e, sg;
                asm("ex2.approx.f32 %0, %1;" : "=f"(e) : "f"(lg * -1.4426950408889634f));
                asm("rcp.approx.f32 %0, %1;" : "=f"(sg) : "f"(1.0f + e));
                s[n] = sg;
            }
            float Pn[NI];
            Pn[0] = 1.f;
            #pragma unroll
            for (int i = 0; i < 15; i++) {
                float gg = s[i];
                Pn[2 * i + 1] = Pn[i] * (1.f - gg);
                Pn[2 * i + 2] = Pn[i] * gg;
            }
            #pragma unroll
            for (int l = 0; l < NL; l++) {
                const int p = (30 + l) >> 1;
                float gg = s[p];
                float pl = Pn[p] * ((l & 1) ? gg : (1.f - gg));
                o0 += pl * sc[2 * l + 0];
                o1 += pl * sc[2 * l + 1];
            }
            (void)Lr;
        }

        {
            const u32 Wb_base = sbase + (u32)wf * 4 + Wb_rel;
            #pragma unroll
            for (int kk = 0; kk < 16; kk++) {
                u32 a[2][4];
                #pragma unroll
                for (int mt = 0; mt < 2; mt++) {
                    const u32 r0 = Xa_base + (u32)(mt * 16 * STX + kk * 8) * 4;
                    asm volatile("ld.shared.u32 %0, [%1];" : "=r"(a[mt][0]) : "r"(r0));
                    asm volatile("ld.shared.u32 %0, [%1];" : "=r"(a[mt][1]) : "r"(r0 + 8 * STX * 4));
                    asm volatile("ld.shared.u32 %0, [%1];" : "=r"(a[mt][2]) : "r"(r0 + 16));
                    asm volatile("ld.shared.u32 %0, [%1];" : "=r"(a[mt][3]) : "r"(r0 + 8 * STX * 4 + 16));
                }
                #pragma unroll
                for (int nt = 0; nt < 4; nt++) {
                    u32 b0, b1;
                    lds_v2(b0, b1, Wb_base + (u32)(nt * 8 * STWS + kk * 8) * 4);
                    MMA_TF32(acc[0][nt], a[0], b0, b1);
                    MMA_TF32(acc[1][nt], a[1], b0, b1);
                }
            }
        }

        __syncthreads();   // epilogue(g-1) L-reads done; GEMM(g) acc complete

        // ---- STS logits(g) into L ----
        {
            float* Ls = smf + L_F;
            #pragma unroll
            for (int mt = 0; mt < 2; mt++)
                #pragma unroll
                for (int nt = 0; nt < 4; nt++) {
                    int r = warp_m * 32 + mt * 16 + gid;
                    int c = warp_n * 32 + nt * 8 + tid4 * 2;
                    Ls[ r      * STL + c    ] = acc[mt][nt][0];
                    Ls[ r      * STL + c + 1] = acc[mt][nt][1];
                    Ls[(r + 8) * STL + c    ] = acc[mt][nt][2];
                    Ls[(r + 8) * STL + c + 1] = acc[mt][nt][3];
                }
        }
    }

    __syncthreads();   // logits(4) visible

    // ---- epilogue for last group ----
    {
        const int t = (NGROUP - 1) * 4 + etl;
        const float* bs = c_bs + t * NI;
        const float* sc = c_sc + t * 64;
        float s[NI];
        #pragma unroll
        for (int n = 0; n < NI; n++) {
            float lv;
            asm volatile("ld.shared.f32 %0, [%1];" : "=f"(lv) : "r"(Lr_base + n * 4));
            float lg = lv + bs[n];
            float e, sg;
            asm("ex2.approx.f32 %0, %1;" : "=f"(e) : "f"(lg * -1.4426950408889634f));
            asm("rcp.approx.f32 %0, %1;" : "=f"(sg) : "f"(1.0f + e));
            s[n] = sg;
        }
        float Pn[NI];
        Pn[0] = 1.f;
        #pragma unroll
        for (int i = 0; i < 15; i++) {
            float gg = s[i];
            Pn[2 * i + 1] = Pn[i] * (1.f - gg);
            Pn[2 * i + 2] = Pn[i] * gg;
        }
        #pragma unroll
        for (int l = 0; l < NL; l++) {
            const int p = (30 + l) >> 1;
            float gg = s[p];
            float pl = Pn[p] * ((l & 1) ? gg : (1.f - gg));
            o0 += pl * sc[2 * l + 0];
            o1 += pl * sc[2 * l + 1];
        }
    }

    // ---- combine 4 tree-partials per row, write out ----
    smf[SP_F + tid * 2 + 0] = o0;
    smf[SP_F + tid * 2 + 1] = o1;
    __syncthreads();
    if (tid < TILE_M) {
        float a0 = 0.f, a1 = 0.f;
        #pragma unroll
        for (int j = 0; j < 4; j++) {
            a0 += smf[SP_F + (tid + j * 64) * 2 + 0];
            a1 += smf[SP_F + (tid + j * 64) * 2 + 1];
        }
        ((float2*)out)[m0 + tid] = make_float2(a0, a1);
    }
}

// ---------------- launch ----------------
extern "C" void kernel_launch(void* const* d_in, const int* in_sizes, int n_in,
                              void* d_out, int out_size)
{
    const float* x  = (const float*)d_in[0];  // [B, 128]
    const float* sw = (const float*)d_in[1];  // [T, 31, 128]
    const float* sb = (const float*)d_in[2];  // [T, 31]
    const float* ll = (const float*)d_in[3];  // [T, 32, 2]
    const float* tw = (const float*)d_in[4];  // [T]
    const float* fm = (const float*)d_in[5];  // [T, 128]

    int T = in_sizes[4];
    if (T > TMAX) T = TMAX;
    int B = in_sizes[0] / F;

    cudaFuncSetAttribute(forest_mma, cudaFuncAttributeMaxDynamicSharedMemorySize, SMEM_BYTES);

    prep<<<(NGROUP * 128 * F + 255) / 256, 256>>>(sw, fm, ll, tw, T);

    // bias + leaf scales into constant memory (D2D async: graph-capturable)
    cudaMemcpyToSymbolAsync(c_bs, sb, (size_t)T * NI * sizeof(float), 0,
                            cudaMemcpyDeviceToDevice, 0);
    void* scp = nullptr;
    cudaGetSymbolAddress(&scp, g_sc);
    cudaMemcpyToSymbolAsync(c_sc, scp, (size_t)TMAX * 64 * sizeof(float), 0,
                            cudaMemcpyDeviceToDevice, 0);

    forest_mma<<<(B + TILE_M - 1) / TILE_M, NTHREADS, SMEM_BYTES>>>(x, (float*)d_out, B);
}

// round 9
// speedup vs baseline: 1.7625x; 1.7625x over previous
#include <cuda_runtime.h>
#include <cuda_fp16.h>
#include <cstdint>

typedef unsigned int u32;
typedef unsigned long long u64;

#define F       128
#define NI      31
#define NL      32
#define TMAX    20
#define NGROUP  5            // 5 groups x 4 trees (128 node-cols per group)
#define TILE_M  128
#define NTHREADS 256

// ---- SMEM layout (bytes) ----
// Row stride for X/W: 72 u32 words (144 fp16, 288B). 72 mod 32 = 8 ->
// LDS.64 lanes (gid 0..7 within half-warp x tid4) hit distinct banks.
#define STW72  72
#define X_OFF  0             // 128 rows * 288B = 36864
#define W_OFF  36864         // 128 nrows * 288B = 36864
#define L_OFF  73728         // 64 rows * 129 words * 4B = 33024 (fp32 logits, half tile)
#define SP_OFF 106752        // 128 rows * 4 trees * 2 classes * 4B = 4096
#define SMEM_BYTES 110848
#define STL    129           // logits row stride (odd -> conflict-free epilogue reads)

// __device__ scratch (allocation-free)
__device__ __half g_Wh[NGROUP * 128 * F];  // fp16 masked weights, k pair-permuted per 16-block
__device__ float  g_sc[TMAX * 64];         // softmax(tree_w)[t] * softmax(leaf_logits)[t,l,:]

__constant__ float c_bs[TMAX * NI];        // split bias
__constant__ float c_sc[TMAX * 64];        // leaf/class scales

// ---------------- helpers ----------------
__device__ __forceinline__ u32 smem_u32(const void* p) {
    u32 a;
    asm("{ .reg .u64 t; cvta.to.shared.u64 t, %1; cvt.u32.u64 %0, t; }" : "=r"(a) : "l"(p));
    return a;
}
__device__ __forceinline__ u32 pack_h2(float lo, float hi) {
    u32 r;
    asm("cvt.rn.f16x2.f32 %0, %1, %2;" : "=r"(r) : "f"(hi), "f"(lo));
    return r;
}
__device__ __forceinline__ void cpa16(u32 dst, const void* src) {
    asm volatile("cp.async.cg.shared.global [%0], [%1], 16;" :: "r"(dst), "l"(src) : "memory");
}
#define CP_COMMIT() asm volatile("cp.async.commit_group;" ::: "memory")
template<int N> __device__ __forceinline__ void cp_wait() {
    asm volatile("cp.async.wait_group %0;" :: "n"(N) : "memory");
}
__device__ __forceinline__ void lds_v2(u32& a, u32& b, u32 addr) {
    asm volatile("ld.shared.v2.u32 {%0,%1}, [%2];" : "=r"(a), "=r"(b) : "r"(addr));
}

// m16n8k16 f16 MMA, fp32 accum. A: 4 regs, B: 2 regs, C/D: 4 f32.
#define MMA_F16(c, a0, a1, a2, a3, b0, b1) \
    asm volatile("mma.sync.aligned.m16n8k16.row.col.f32.f16.f16.f32 " \
        "{%0,%1,%2,%3}, {%4,%5,%6,%7}, {%8,%9}, {%0,%1,%2,%3};" \
        : "+f"((c)[0]), "+f"((c)[1]), "+f"((c)[2]), "+f"((c)[3]) \
        : "r"(a0), "r"(a1), "r"(a2), "r"(a3), "r"(b0), "r"(b1))

// ---------------- prologue ----------------
// k-permutation within each 16-k block: thread t4 reads slots 4t4..4t4+3 which
// hold k = {2t4, 2t4+1, 2t4+8, 2t4+9} -> one LDS.64 per fragment pair.
__global__ void prep(const float* __restrict__ sw, const float* __restrict__ fm,
                     const float* __restrict__ ll, const float* __restrict__ tw, int T) {
    int idx = blockIdx.x * 256 + threadIdx.x;
    const int total = NGROUP * 128 * F;   // 81920
    if (idx < total) {
        int k    = idx & 127;
        int nrow = (idx >> 7) & 127;
        int g    = idx >> 14;
        int t    = g * 4 + (nrow >> 5);
        int n    = nrow & 31;
        float v = 0.f;
        if (t < T && n < NI) v = sw[(t * NI + n) * F + k] * fm[t * F + k];
        int k16 = k & 15;
        int slot = ((k16 & 7) >> 1) * 4 + ((k16 >> 3) & 1) * 2 + (k16 & 1);
        g_Wh[(idx & ~127) + (k & ~15) + slot] = __float2half_rn(v);
    }
    if (idx < TMAX * NL) {
        int t = idx >> 5, l = idx & 31;
        float w0 = 0.f, w1 = 0.f;
        if (t < T) {
            float m = -1e30f;
            for (int k = 0; k < T; k++) m = fmaxf(m, tw[k]);
            float den = 0.f;
            for (int k = 0; k < T; k++) den += expf(tw[k] - m);
            float w = expf(tw[t] - m) / den;
            float a = ll[(t * NL + l) * 2 + 0];
            float b = ll[(t * NL + l) * 2 + 1];
            float mm = fmaxf(a, b);
            float ea = expf(a - mm), eb = expf(b - mm);
            float inv = w / (ea + eb);
            w0 = ea * inv; w1 = eb * inv;
        }
        g_sc[t * 64 + l * 2 + 0] = w0;
        g_sc[t * 64 + l * 2 + 1] = w1;
    }
}

// ---------------- main fused kernel ----------------
// TILE_M=128, 256 threads = 8 warps as 2(M)x4(N), per warp 4 mt x 4 nt m16n8k16.
// X fp16 resident (converted in-kernel); W single buffer, cp.async prefetch of
// W(g+1) overlapped with epilogue(g). Epilogue in two 64-row halves through a
// shared fp32 logits buffer. 2 CTAs/SM.
__global__ void __launch_bounds__(NTHREADS, 2) forest_mma(
    const float* __restrict__ x, float* __restrict__ out, int B)
{
    extern __shared__ char smem[];
    float* smf = (float*)smem;
    const u32 sbase = smem_u32(smem);
    const int tid  = threadIdx.x;
    const int lane = tid & 31;
    const int wid  = tid >> 5;
    const int gid  = lane >> 2;
    const int tid4 = lane & 3;
    const int warp_m = wid & 1;      // 2 M-groups of 64 rows (4 mt tiles)
    const int warp_n = wid >> 1;     // 4 N-groups of 32 cols (4 nt tiles)
    const int m0 = blockIdx.x * TILE_M;

    // ---- issue cp.async for W group 0 ----
    {
        const __half* src = g_Wh;
        #pragma unroll
        for (int j = 0; j < 8; j++) {
            int i = tid + j * NTHREADS;           // 2048 chunks: row = i>>4, c = i&15
            int row = i >> 4, c = i & 15;
            cpa16(sbase + W_OFF + (u32)(row * STW72 * 4) + c * 16, src + row * F + c * 8);
        }
        CP_COMMIT();
    }

    // ---- stage X: LDG float4 -> fp16 pairs at permuted slots ----
    {
        #pragma unroll
        for (int j = 0; j < 16; j++) {
            int i = tid + j * NTHREADS;           // 4096 float4: row = i>>5, c = i&31
            int row = i >> 5, c = i & 31;
            int srow = m0 + row; if (srow >= B) srow = B - 1;
            float4 v = ((const float4*)(x + (size_t)srow * F))[c];
            u32 h01 = pack_h2(v.x, v.y);
            u32 h23 = pack_h2(v.z, v.w);
            int kb = c >> 2, jj = c & 3;
            int wbase = (jj & 1) * 4 + (jj >> 1);           // {0,4,1,5}
            u32 waddr = sbase + X_OFF + (u32)((row * STW72 + kb * 8 + wbase) * 4);
            asm volatile("st.shared.u32 [%0], %1;" :: "r"(waddr), "r"(h01));
            asm volatile("st.shared.u32 [%0], %1;" :: "r"(waddr + 8), "r"(h23));
        }
    }

    const int h   = tid & 63;        // epilogue slot within half
    const int etl = tid >> 6;        // tree-in-group (warp-uniform)
    float oc[2][2] = {{0.f, 0.f}, {0.f, 0.f}};   // [q][class]

    // per-thread fragment base addresses
    const u32 Abase = sbase + X_OFF + (u32)(((warp_m * 64 + gid) * STW72 + tid4 * 2) * 4);
    const u32 Bbase = sbase + W_OFF + (u32)(((warp_n * 32 + gid) * STW72 + tid4 * 2) * 4);
    const u32 Lread = sbase + L_OFF + (u32)((h * STL + etl * 32) * 4);

    #pragma unroll 1
    for (int g = 0; g < NGROUP; g++) {
        cp_wait<0>();
        __syncthreads();             // W(g) + (g==0) X visible; L(g-1) epi reads done

        // ================= GEMM(g) =================
        float acc[4][4][4];
        #pragma unroll
        for (int mt = 0; mt < 4; mt++)
            #pragma unroll
            for (int nt = 0; nt < 4; nt++)
                #pragma unroll
                for (int q = 0; q < 4; q++) acc[mt][nt][q] = 0.f;

        #pragma unroll
        for (int kk = 0; kk < 8; kk++) {
            u32 a[4][4];
            #pragma unroll
            for (int mt = 0; mt < 4; mt++) {
                const u32 r0 = Abase + (u32)((mt * 16 * STW72 + kk * 8) * 4);
                lds_v2(a[mt][0], a[mt][2], r0);                       // row gid:   a0,a2
                lds_v2(a[mt][1], a[mt][3], r0 + 8 * STW72 * 4);       // row gid+8: a1,a3
            }
            #pragma unroll
            for (int nt = 0; nt < 4; nt++) {
                u32 b0, b1;
                lds_v2(b0, b1, Bbase + (u32)((nt * 8 * STW72 + kk * 8) * 4));
                #pragma unroll
                for (int mt = 0; mt < 4; mt++)
                    MMA_F16(acc[mt][nt], a[mt][0], a[mt][1], a[mt][2], a[mt][3], b0, b1);
            }
        }

        __syncthreads();             // all W(g) reads complete

        // prefetch W(g+1) into the (now free) single W buffer; overlaps epilogue
        if (g < NGROUP - 1) {
            const __half* src = g_Wh + (size_t)(g + 1) * 128 * F;
            #pragma unroll
            for (int j = 0; j < 8; j++) {
                int i = tid + j * NTHREADS;
                int row = i >> 4, c = i & 15;
                cpa16(sbase + W_OFF + (u32)(row * STW72 * 4) + c * 16, src + row * F + c * 8);
            }
            CP_COMMIT();
        }

        // ===== two epilogue halves through the 64-row logits buffer =====
        #pragma unroll
        for (int q = 0; q < 2; q++) {
            // store logits: mt = 2q, 2q+1 (actual rows warp_m*64 + 32q + [0,32))
            #pragma unroll
            for (int e = 0; e < 2; e++) {
                const int mt = 2 * q + e;
                const int lrow = warp_m * 32 + e * 16 + gid;
                const int col  = warp_n * 32 + tid4 * 2;
                #pragma unroll
                for (int nt = 0; nt < 4; nt++) {
                    smf[L_OFF / 4 +  lrow      * STL + col + nt * 8    ] = acc[mt][nt][0];
                    smf[L_OFF / 4 +  lrow      * STL + col + nt * 8 + 1] = acc[mt][nt][1];
                    smf[L_OFF / 4 + (lrow + 8) * STL + col + nt * 8    ] = acc[mt][nt][2];
                    smf[L_OFF / 4 + (lrow + 8) * STL + col + nt * 8 + 1] = acc[mt][nt][3];
                }
            }
            __syncthreads();         // logits visible

            // epilogue: one (row, tree) task per thread
            {
                const int t = g * 4 + etl;
                const float* bs = c_bs + t * NI;
                const float* sc = c_sc + t * 64;
                float s[NI];
                #pragma unroll
                for (int n = 0; n < NI; n++) {
                    float lv;
                    asm volatile("ld.shared.f32 %0, [%1];" : "=f"(lv) : "r"(Lread + n * 4));
                    float hlf = 0.5f * (lv + bs[n]);
                    float th;
                    asm("tanh.approx.f32 %0, %1;" : "=f"(th) : "f"(hlf));
                    s[n] = 0.5f * th + 0.5f;      // sigmoid
                }
                float Pn[NI];
                Pn[0] = 1.f;
                #pragma unroll
                for (int i = 0; i < 15; i++) {
                    float gg = s[i];
                    float pr = Pn[i] * gg;
                    Pn[2 * i + 2] = pr;           // right child (even node)
                    Pn[2 * i + 1] = Pn[i] - pr;   // left child
                }
                float a0 = 0.f, a1 = 0.f;
                #pragma unroll
                for (int l = 0; l < NL; l += 2) {
                    const int p = (30 + l) >> 1;  // parent of leaf pair
                    float gg = s[p];
                    float pr = Pn[p] * gg;        // right sibling (l+1)
                    float pf = Pn[p] - pr;        // left sibling (l)
                    a0 += pf * sc[2 * l + 0] + pr * sc[2 * l + 2];
                    a1 += pf * sc[2 * l + 1] + pr * sc[2 * l + 3];
                }
                oc[q][0] += a0;
                oc[q][1] += a1;
            }
            __syncthreads();         // epi reads done before q=1 store / next GEMM's L store
        }
    }

    // ---- write per-(row, tree) partials, reduce 4 trees per row ----
    #pragma unroll
    for (int q = 0; q < 2; q++) {
        const int row = (h >> 5) * 64 + 32 * q + (h & 31);
        smf[SP_OFF / 4 + (row * 4 + etl) * 2 + 0] = oc[q][0];
        smf[SP_OFF / 4 + (row * 4 + etl) * 2 + 1] = oc[q][1];
    }
    __syncthreads();
    if (tid < TILE_M) {
        float a0 = 0.f, a1 = 0.f;
        #pragma unroll
        for (int e = 0; e < 4; e++) {
            a0 += smf[SP_OFF / 4 + (tid * 4 + e) * 2 + 0];
            a1 += smf[SP_OFF / 4 + (tid * 4 + e) * 2 + 1];
        }
        int row = m0 + tid;
        if (row < B) ((float2*)out)[row] = make_float2(a0, a1);
    }
}

// ---------------- launch ----------------
extern "C" void kernel_launch(void* const* d_in, const int* in_sizes, int n_in,
                              void* d_out, int out_size)
{
    const float* x  = (const float*)d_in[0];  // [B, 128]
    const float* sw = (const float*)d_in[1];  // [T, 31, 128]
    const float* sb = (const float*)d_in[2];  // [T, 31]
    const float* ll = (const float*)d_in[3];  // [T, 32, 2]
    const float* tw = (const float*)d_in[4];  // [T]
    const float* fm = (const float*)d_in[5];  // [T, 128]

    int T = in_sizes[4];
    if (T > TMAX) T = TMAX;
    int B = in_sizes[0] / F;

    cudaFuncSetAttribute(forest_mma, cudaFuncAttributeMaxDynamicSharedMemorySize, SMEM_BYTES);

    prep<<<(NGROUP * 128 * F + 255) / 256, 256>>>(sw, fm, ll, tw, T);

    cudaMemcpyToSymbolAsync(c_bs, sb, (size_t)T * NI * sizeof(float), 0,
                            cudaMemcpyDeviceToDevice, 0);
    void* scp = nullptr;
    cudaGetSymbolAddress(&scp, g_sc);
    cudaMemcpyToSymbolAsync(c_sc, scp, (size_t)TMAX * 64 * sizeof(float), 0,
                            cudaMemcpyDeviceToDevice, 0);

    forest_mma<<<(B + TILE_M - 1) / TILE_M, NTHREADS, SMEM_BYTES>>>(x, (float*)d_out, B);
}

// round 11
// speedup vs baseline: 2.0718x; 1.1755x over previous
#include <cuda_runtime.h>
#include <cuda_fp16.h>
#include <cstdint>

typedef unsigned int u32;
typedef unsigned long long u64;

#define F       128
#define NI      31
#define NL      32
#define TMAX    20
#define NGROUP  5            // 5 groups x 4 trees (128 node-cols per group)
#define TILE_M  128
#define NTHREADS 256

// ---- SMEM layout (bytes) ----
// X/W row stride: 72 u32 words (144 fp16, 288B). 72 mod 32 = 8 -> conflict-free LDS.64.
#define STW72  72
#define X_OFF  0             // 128 rows * 288B = 36864 (reused as SP at the end)
#define W_OFF  36864         // 128 nrows * 288B = 36864
#define L_OFF  73728         // 128 rows * 20 quads * 16B = 40960 (fp16 logits, quad-swizzled)
#define SMEM_BYTES 114688
// L quad layout: quad = row*20 + tree*4 + (t4 ^ ((row>>1)&3)); quad holds 4 h2 (nt=0..3)

// __device__ scratch (allocation-free)
__device__ __half g_Wh[NGROUP * 128 * F];  // fp16 masked weights, k pair-permuted per 16-block
__device__ float  g_sc[TMAX * 64];         // softmax(tree_w)[t] * softmax(leaf_logits)[t,l,:]

__constant__ float c_bs[TMAX * NI + 8];    // split bias (padded, zero-init)
__constant__ float c_sc[TMAX * 64];        // leaf/class scales

// ---------------- helpers ----------------
__device__ __forceinline__ u32 smem_u32(const void* p) {
    u32 a;
    asm("{ .reg .u64 t; cvta.to.shared.u64 t, %1; cvt.u32.u64 %0, t; }" : "=r"(a) : "l"(p));
    return a;
}
__device__ __forceinline__ u32 pack_h2(float lo, float hi) {
    u32 r;
    asm("cvt.rn.f16x2.f32 %0, %1, %2;" : "=r"(r) : "f"(hi), "f"(lo));
    return r;
}
__device__ __forceinline__ void cpa16(u32 dst, const void* src) {
    asm volatile("cp.async.cg.shared.global [%0], [%1], 16;" :: "r"(dst), "l"(src) : "memory");
}
#define CP_COMMIT() asm volatile("cp.async.commit_group;" ::: "memory")
template<int N> __device__ __forceinline__ void cp_wait() {
    asm volatile("cp.async.wait_group %0;" :: "n"(N) : "memory");
}
__device__ __forceinline__ void lds_v2(u32& a, u32& b, u32 addr) {
    asm volatile("ld.shared.v2.u32 {%0,%1}, [%2];" : "=r"(a), "=r"(b) : "r"(addr));
}
__device__ __forceinline__ void lds_v4(u32& a, u32& b, u32& c, u32& d, u32 addr) {
    asm volatile("ld.shared.v4.u32 {%0,%1,%2,%3}, [%4];"
                 : "=r"(a), "=r"(b), "=r"(c), "=r"(d) : "r"(addr));
}
__device__ __forceinline__ void sts_v4(u32 addr, u32 a, u32 b, u32 c, u32 d) {
    asm volatile("st.shared.v4.u32 [%0], {%1,%2,%3,%4};"
                 :: "r"(addr), "r"(a), "r"(b), "r"(c), "r"(d) : "memory");
}

// m16n8k16 f16 MMA, fp32 accum.
#define MMA_F16(c, a0, a1, a2, a3, b0, b1) \
    asm volatile("mma.sync.aligned.m16n8k16.row.col.f32.f16.f16.f32 " \
        "{%0,%1,%2,%3}, {%4,%5,%6,%7}, {%8,%9}, {%0,%1,%2,%3};" \
        : "+f"((c)[0]), "+f"((c)[1]), "+f"((c)[2]), "+f"((c)[3]) \
        : "r"(a0), "r"(a1), "r"(a2), "r"(a3), "r"(b0), "r"(b1))

// ---------------- prologue ----------------
// k-permutation within each 16-k block so a lane's B fragment is one LDS.64.
__global__ void prep(const float* __restrict__ sw, const float* __restrict__ fm,
                     const float* __restrict__ ll, const float* __restrict__ tw, int T) {
    int idx = blockIdx.x * 256 + threadIdx.x;
    const int total = NGROUP * 128 * F;   // 81920
    if (idx < total) {
        int k    = idx & 127;
        int nrow = (idx >> 7) & 127;
        int g    = idx >> 14;
        int t    = g * 4 + (nrow >> 5);
        int n    = nrow & 31;
        float v = 0.f;
        if (t < T && n < NI) v = sw[(t * NI + n) * F + k] * fm[t * F + k];
        int k16 = k & 15;
        int slot = ((k16 & 7) >> 1) * 4 + ((k16 >> 3) & 1) * 2 + (k16 & 1);
        g_Wh[(idx & ~127) + (k & ~15) + slot] = __float2half_rn(v);
    }
    if (idx < TMAX * NL) {
        int t = idx >> 5, l = idx & 31;
        float w0 = 0.f, w1 = 0.f;
        if (t < T) {
            float m = -1e30f;
            for (int k = 0; k < T; k++) m = fmaxf(m, tw[k]);
            float den = 0.f;
            for (int k = 0; k < T; k++) den += expf(tw[k] - m);
            float w = expf(tw[t] - m) / den;
            float a = ll[(t * NL + l) * 2 + 0];
            float b = ll[(t * NL + l) * 2 + 1];
            float mm = fmaxf(a, b);
            float ea = expf(a - mm), eb = expf(b - mm);
            float inv = w / (ea + eb);
            w0 = ea * inv; w1 = eb * inv;
        }
        g_sc[t * 64 + l * 2 + 0] = w0;
        g_sc[t * 64 + l * 2 + 1] = w1;
    }
}

// ---------------- main fused kernel ----------------
// TILE_M=128, 256 threads = 8 warps as 2(M)x4(N). Per group:
//   [GEMM] sync [cp.async W(g+1); pack+STS.128 fp16 logits] sync [LDS.128 + bias
//   + tanh-sigmoid + path product] -> loop-top sync. 3 barriers/group, 2 CTAs/SM.
__global__ void __launch_bounds__(NTHREADS, 2) forest_mma(
    const float* __restrict__ x, float* __restrict__ out, int B)
{
    extern __shared__ char smem[];
    float* smf = (float*)smem;
    const u32 sbase = smem_u32(smem);
    const int tid  = threadIdx.x;
    const int lane = tid & 31;
    const int wid  = tid >> 5;
    const int gid  = lane >> 2;
    const int tid4 = lane & 3;
    const int warp_m = wid & 1;      // 2 M-groups of 64 rows
    const int warp_n = wid >> 1;     // 4 N-groups of 32 cols (= tree-in-group)
    const int m0 = blockIdx.x * TILE_M;

    // ---- cp.async W group 0 ----
    {
        const __half* src = g_Wh;
        #pragma unroll
        for (int j = 0; j < 8; j++) {
            int i = tid + j * NTHREADS;
            int row = i >> 4, c = i & 15;
            cpa16(sbase + W_OFF + (u32)(row * STW72 * 4) + c * 16, src + row * F + c * 8);
        }
        CP_COMMIT();
    }

    // ---- stage X: LDG float4 -> fp16 pairs at permuted slots ----
    {
        #pragma unroll
        for (int j = 0; j < 16; j++) {
            int i = tid + j * NTHREADS;
            int row = i >> 5, c = i & 31;
            int srow = m0 + row; if (srow >= B) srow = B - 1;
            float4 v = ((const float4*)(x + (size_t)srow * F))[c];
            u32 h01 = pack_h2(v.x, v.y);
            u32 h23 = pack_h2(v.z, v.w);
            int kb = c >> 2, jj = c & 3;
            int wbase = (jj & 1) * 4 + (jj >> 1);
            u32 waddr = sbase + X_OFF + (u32)((row * STW72 + kb * 8 + wbase) * 4);
            asm volatile("st.shared.u32 [%0], %1;" :: "r"(waddr), "r"(h01));
            asm volatile("st.shared.u32 [%0], %1;" :: "r"(waddr + 8), "r"(h23));
        }
    }

    // fragment bases
    const u32 Abase = sbase + X_OFF + (u32)(((warp_m * 64 + gid) * STW72 + tid4 * 2) * 4);
    const u32 Bbase = sbase + W_OFF + (u32)(((warp_n * 32 + gid) * STW72 + tid4 * 2) * 4);

    // reader identity: row r, tree pair
    const int r    = tid & 127;
    const int jhi  = tid >> 7;             // 0/1 -> trees {0,1} or {2,3} of group
    const int sr   = (r >> 1) & 3;         // quad swizzle key for this row
    const u32 Rrow = sbase + L_OFF + (u32)(r * 20 * 16);

    float oc[2][2] = {{0.f, 0.f}, {0.f, 0.f}};   // [tree-in-pair][class]

    #pragma unroll 1
    for (int g = 0; g < NGROUP; g++) {
        cp_wait<0>();
        __syncthreads();             // W(g) (+X on g=0) visible; L(g-1) reads done

        // ================= GEMM(g) =================
        float acc[4][4][4];
        #pragma unroll
        for (int mt = 0; mt < 4; mt++)
            #pragma unroll
            for (int nt = 0; nt < 4; nt++)
                #pragma unroll
                for (int q = 0; q < 4; q++) acc[mt][nt][q] = 0.f;

        #pragma unroll
        for (int kk = 0; kk < 8; kk++) {
            u32 a[4][4];
            #pragma unroll
            for (int mt = 0; mt < 4; mt++) {
                const u32 r0 = Abase + (u32)((mt * 16 * STW72 + kk * 8) * 4);
                lds_v2(a[mt][0], a[mt][2], r0);
                lds_v2(a[mt][1], a[mt][3], r0 + 8 * STW72 * 4);
            }
            #pragma unroll
            for (int nt = 0; nt < 4; nt++) {
                u32 b0, b1;
                lds_v2(b0, b1, Bbase + (u32)((nt * 8 * STW72 + kk * 8) * 4));
                #pragma unroll
                for (int mt = 0; mt < 4; mt++)
                    MMA_F16(acc[mt][nt], a[mt][0], a[mt][1], a[mt][2], a[mt][3], b0, b1);
            }
        }

        __syncthreads();             // W(g) reads complete -> buffer free

        // prefetch W(g+1) (overlaps logits store + epilogue)
        if (g < NGROUP - 1) {
            const __half* src = g_Wh + (size_t)(g + 1) * 128 * F;
            #pragma unroll
            for (int j = 0; j < 8; j++) {
                int i = tid + j * NTHREADS;
                int row = i >> 4, c = i & 15;
                cpa16(sbase + W_OFF + (u32)(row * STW72 * 4) + c * 16, src + row * F + c * 8);
            }
            CP_COMMIT();
        }

        // ---- pack fp16 logits, STS.128 (8 per thread, conflict-free) ----
        #pragma unroll
        for (int mt = 0; mt < 4; mt++) {
            #pragma unroll
            for (int half = 0; half < 2; half++) {
                const int row = warp_m * 64 + mt * 16 + half * 8 + gid;
                u32 h0 = pack_h2(acc[mt][0][2 * half], acc[mt][0][2 * half + 1]);
                u32 h1 = pack_h2(acc[mt][1][2 * half], acc[mt][1][2 * half + 1]);
                u32 h2 = pack_h2(acc[mt][2][2 * half], acc[mt][2][2 * half + 1]);
                u32 h3 = pack_h2(acc[mt][3][2 * half], acc[mt][3][2 * half + 1]);
                u32 quad = (u32)(row * 20 + warp_n * 4 + (tid4 ^ ((row >> 1) & 3)));
                sts_v4(sbase + L_OFF + quad * 16, h0, h1, h2, h3);
            }
        }
        __syncthreads();             // logits(g) visible

        // ---- epilogue: 2 (row, tree) tasks per thread ----
        #pragma unroll
        for (int j2 = 0; j2 < 2; j2++) {
            const int tp = jhi * 2 + j2;        // tree-in-group 0..3
            const int t  = g * 4 + tp;
            const float* bs = c_bs + t * NI;
            const float* sc = c_sc + t * 64;
            float s[32];
            #pragma unroll
            for (int q = 0; q < 4; q++) {       // logical quad = writer's tid4
                u32 w0, w1, w2, w3;
                lds_v4(w0, w1, w2, w3, Rrow + (u32)(tp * 4 + (q ^ sr)) * 16);
                const u32 ws[4] = {w0, w1, w2, w3};
                #pragma unroll
                for (int nt = 0; nt < 4; nt++) {
                    __half2 hv = *(__half2*)&ws[nt];
                    const int n = nt * 8 + 2 * q;
                    s[n]     = __low2float(hv);
                    s[n + 1] = __high2float(hv);
                }
            }
            // bias + sigmoid (tanh form), nodes 0..30
            #pragma unroll
            for (int n = 0; n < NI; n++) {
                float hlf = 0.5f * (s[n] + bs[n]);
                float th;
                asm("tanh.approx.f32 %0, %1;" : "=f"(th) : "f"(hlf));
                s[n] = 0.5f * th + 0.5f;
            }
            float Pn[NI];
            Pn[0] = 1.f;
            #pragma unroll
            for (int i = 0; i < 15; i++) {
                float gg = s[i];
                float pr = Pn[i] * gg;
                Pn[2 * i + 2] = pr;
                Pn[2 * i + 1] = Pn[i] - pr;
            }
            float a0 = 0.f, a1 = 0.f;
            #pragma unroll
            for (int l = 0; l < NL; l += 2) {
                const int p = (30 + l) >> 1;
                float gg = s[p];
                float pr = Pn[p] * gg;
                float pf = Pn[p] - pr;
                a0 += pf * sc[2 * l + 0] + pr * sc[2 * l + 2];
                a1 += pf * sc[2 * l + 1] + pr * sc[2 * l + 3];
            }
            oc[j2][0] += a0;
            oc[j2][1] += a1;
        }
    }

    // ---- reduce 2 thread-partials per row (X region reused as scratch) ----
    __syncthreads();
    smf[r * 4 + jhi * 2 + 0] = oc[0][0] + oc[1][0];
    smf[r * 4 + jhi * 2 + 1] = oc[0][1] + oc[1][1];
    __syncthreads();
    if (tid < TILE_M) {
        float a0 = smf[tid * 4 + 0] + smf[tid * 4 + 2];
        float a1 = smf[tid * 4 + 1] + smf[tid * 4 + 3];
        int row = m0 + tid;
        if (row < B) ((float2*)out)[row] = make_float2(a0, a1);
    }
}

// ---------------- launch ----------------
extern "C" void kernel_launch(void* const* d_in, const int* in_sizes, int n_in,
                              void* d_out, int out_size)
{
    const float* x  = (const float*)d_in[0];  // [B, 128]
    const float* sw = (const float*)d_in[1];  // [T, 31, 128]
    const float* sb = (const float*)d_in[2];  // [T, 31]
    const float* ll = (const float*)d_in[3];  // [T, 32, 2]
    const float* tw = (const float*)d_in[4];  // [T]
    const float* fm = (const float*)d_in[5];  // [T, 128]

    int T = in_sizes[4];
    if (T > TMAX) T = TMAX;
    int B = in_sizes[0] / F;

    cudaFuncSetAttribute(forest_mma, cudaFuncAttributeMaxDynamicSharedMemorySize, SMEM_BYTES);

    prep<<<(NGROUP * 128 * F + 255) / 256, 256>>>(sw, fm, ll, tw, T);

    cudaMemcpyToSymbolAsync(c_bs, sb, (size_t)T * NI * sizeof(float), 0,
                            cudaMemcpyDeviceToDevice, 0);
    void* scp = nullptr;
    cudaGetSymbolAddress(&scp, g_sc);
    cudaMemcpyToSymbolAsync(c_sc, scp, (size_t)TMAX * 64 * sizeof(float), 0,
                            cudaMemcpyDeviceToDevice, 0);

    forest_mma<<<(B + TILE_M - 1) / TILE_M, NTHREADS, SMEM_BYTES>>>(x, (float*)d_out, B);
}

// round 12
// speedup vs baseline: 2.3815x; 1.1495x over previous
#include <cuda_runtime.h>
#include <cuda_fp16.h>
#include <cstdint>

typedef unsigned int u32;
typedef unsigned long long u64;

#define F       128
#define NI      31
#define NL      32
#define TMAX    20
#define NGROUP  5            // 5 groups x 4 trees (128 node-cols per group)
#define TILE_M  128
#define NTHREADS 256

// ---- SMEM layout (bytes) ----
// X/W row stride: 72 u32 words (144 fp16, 288B). 72 mod 32 = 8 -> conflict-free LDS.64.
#define STW72  72
#define X_OFF  0             // 128 rows * 288B = 36864 (reused as reduce scratch at the end)
#define W_OFF  36864         // 128 nrows * 288B = 36864
#define L_OFF  73728         // 128 rows * 20 quads * 16B = 40960 (fp16 half-logits, quad-swizzled)
#define SMEM_BYTES 114688
// L quad layout: quad = row*20 + tree*4 + (t4 ^ ((row>>1)&3)); quad holds 4 h2 (nt=0..3)

// __device__ scratch (allocation-free)
__device__ __half g_Wh[NGROUP * 128 * F];  // fp16 HALVED masked weights, k pair-permuted per 16-block
__device__ float  g_bs[TMAX * 32];         // 0.5*bias, padded to 32 nodes
__device__ float  g_lc[TMAX * 32];         // leaf pairs: {base_l, delta_l} for class 0
__device__ float  g_wt[TMAX];              // softmax tree weight

__constant__ float c_bs05[TMAX * 32];      // 0.5*bias per (tree, node-col)
__constant__ float c_lc[TMAX * 32];        // leaf lerp constants
__constant__ float c_wt[TMAX];             // tree weights

// ---------------- helpers ----------------
__device__ __forceinline__ u32 smem_u32(const void* p) {
    u32 a;
    asm("{ .reg .u64 t; cvta.to.shared.u64 t, %1; cvt.u32.u64 %0, t; }" : "=r"(a) : "l"(p));
    return a;
}
__device__ __forceinline__ u32 pack_h2(float lo, float hi) {
    u32 r;
    asm("cvt.rn.f16x2.f32 %0, %1, %2;" : "=r"(r) : "f"(hi), "f"(lo));
    return r;
}
__device__ __forceinline__ void cpa16(u32 dst, const void* src) {
    asm volatile("cp.async.cg.shared.global [%0], [%1], 16;" :: "r"(dst), "l"(src) : "memory");
}
#define CP_COMMIT() asm volatile("cp.async.commit_group;" ::: "memory")
template<int N> __device__ __forceinline__ void cp_wait() {
    asm volatile("cp.async.wait_group %0;" :: "n"(N) : "memory");
}
__device__ __forceinline__ void lds_v2(u32& a, u32& b, u32 addr) {
    asm volatile("ld.shared.v2.u32 {%0,%1}, [%2];" : "=r"(a), "=r"(b) : "r"(addr));
}
__device__ __forceinline__ void lds_v4(u32& a, u32& b, u32& c, u32& d, u32 addr) {
    asm volatile("ld.shared.v4.u32 {%0,%1,%2,%3}, [%4];"
                 : "=r"(a), "=r"(b), "=r"(c), "=r"(d) : "r"(addr));
}
__device__ __forceinline__ void sts_v4(u32 addr, u32 a, u32 b, u32 c, u32 d) {
    asm volatile("st.shared.v4.u32 [%0], {%1,%2,%3,%4};"
                 :: "r"(addr), "r"(a), "r"(b), "r"(c), "r"(d) : "memory");
}

// m16n8k16 f16 MMA, fp32 accum.
#define MMA_F16(c, a0, a1, a2, a3, b0, b1) \
    asm volatile("mma.sync.aligned.m16n8k16.row.col.f32.f16.f16.f32 " \
        "{%0,%1,%2,%3}, {%4,%5,%6,%7}, {%8,%9}, {%0,%1,%2,%3};" \
        : "+f"((c)[0]), "+f"((c)[1]), "+f"((c)[2]), "+f"((c)[3]) \
        : "r"(a0), "r"(a1), "r"(a2), "r"(a3), "r"(b0), "r"(b1))

// ---------------- prologue ----------------
__global__ void prep(const float* __restrict__ sw, const float* __restrict__ fm,
                     const float* __restrict__ sb,
                     const float* __restrict__ ll, const float* __restrict__ tw, int T) {
    int idx = blockIdx.x * 256 + threadIdx.x;
    const int total = NGROUP * 128 * F;   // 81920
    if (idx < total) {
        int k    = idx & 127;
        int nrow = (idx >> 7) & 127;
        int g    = idx >> 14;
        int t    = g * 4 + (nrow >> 5);
        int n    = nrow & 31;
        float v = 0.f;
        if (t < T && n < NI) v = 0.5f * sw[(t * NI + n) * F + k] * fm[t * F + k];
        int k16 = k & 15;
        int slot = ((k16 & 7) >> 1) * 4 + ((k16 >> 3) & 1) * 2 + (k16 & 1);
        g_Wh[(idx & ~127) + (k & ~15) + slot] = __float2half_rn(v);
    }
    if (idx < TMAX * 32) {   // halved bias, node 31 padded to 0
        int t = idx >> 5, n = idx & 31;
        g_bs[idx] = (t < T && n < NI) ? 0.5f * sb[t * NI + n] : 0.f;
    }
    if (idx < TMAX * 16) {   // leaf lerp constants (class 0)
        int t = idx >> 4, l = idx & 15;
        float base = 0.f, delta = 0.f;
        if (t < T) {
            float m = -1e30f;
            for (int k = 0; k < T; k++) m = fmaxf(m, tw[k]);
            float den = 0.f;
            for (int k = 0; k < T; k++) den += expf(tw[k] - m);
            float w = expf(tw[t] - m) / den;
            float a0 = ll[(t * NL + 2 * l) * 2 + 0], b0 = ll[(t * NL + 2 * l) * 2 + 1];
            float a1 = ll[(t * NL + 2 * l + 1) * 2 + 0], b1 = ll[(t * NL + 2 * l + 1) * 2 + 1];
            float m0 = fmaxf(a0, b0), m1 = fmaxf(a1, b1);
            float e0 = expf(a0 - m0), f0 = expf(b0 - m0);
            float e1 = expf(a1 - m1), f1 = expf(b1 - m1);
            float p0 = w * e0 / (e0 + f0);   // class0 prob of leaf 2l (scaled)
            float p1 = w * e1 / (e1 + f1);   // class0 prob of leaf 2l+1 (scaled)
            base = p0; delta = p1 - p0;
        }
        g_lc[t * 32 + 2 * l + 0] = base;
        g_lc[t * 32 + 2 * l + 1] = delta;
    }
    if (idx < TMAX) {        // tree weights
        float w = 0.f;
        if (idx < T) {
            float m = -1e30f;
            for (int k = 0; k < T; k++) m = fmaxf(m, tw[k]);
            float den = 0.f;
            for (int k = 0; k < T; k++) den += expf(tw[k] - m);
            w = expf(tw[idx] - m) / den;
        }
        g_wt[idx] = w;
    }
}

// ---------------- main fused kernel ----------------
// TILE_M=128, 256 threads = 8 warps as 2(M)x4(N). acc initialized to 0.5*bias;
// weights pre-halved -> stored logits are l/2. Epilogue: tanh-sigmoid + path
// product + lerp-folded leaf contraction; class1 = w_t - class0. 2 CTAs/SM.
__global__ void __launch_bounds__(NTHREADS, 2) forest_mma(
    const float* __restrict__ x, float* __restrict__ out, int B)
{
    extern __shared__ char smem[];
    float* smf = (float*)smem;
    const u32 sbase = smem_u32(smem);
    const int tid  = threadIdx.x;
    const int lane = tid & 31;
    const int wid  = tid >> 5;
    const int gid  = lane >> 2;
    const int tid4 = lane & 3;
    const int warp_m = wid & 1;      // 2 M-groups of 64 rows
    const int warp_n = wid >> 1;     // 4 N-groups of 32 cols (= tree-in-group)
    const int m0 = blockIdx.x * TILE_M;

    // ---- cp.async W group 0 ----
    {
        const __half* src = g_Wh;
        #pragma unroll
        for (int j = 0; j < 8; j++) {
            int i = tid + j * NTHREADS;
            int row = i >> 4, c = i & 15;
            cpa16(sbase + W_OFF + (u32)(row * STW72 * 4) + c * 16, src + row * F + c * 8);
        }
        CP_COMMIT();
    }

    // ---- stage X: LDG float4 -> fp16 pairs at permuted slots ----
    {
        #pragma unroll
        for (int j = 0; j < 16; j++) {
            int i = tid + j * NTHREADS;
            int row = i >> 5, c = i & 31;
            int srow = m0 + row; if (srow >= B) srow = B - 1;
            float4 v = ((const float4*)(x + (size_t)srow * F))[c];
            u32 h01 = pack_h2(v.x, v.y);
            u32 h23 = pack_h2(v.z, v.w);
            int kb = c >> 2, jj = c & 3;
            int wbase = (jj & 1) * 4 + (jj >> 1);
            u32 waddr = sbase + X_OFF + (u32)((row * STW72 + kb * 8 + wbase) * 4);
            asm volatile("st.shared.u32 [%0], %1;" :: "r"(waddr), "r"(h01));
            asm volatile("st.shared.u32 [%0], %1;" :: "r"(waddr + 8), "r"(h23));
        }
    }

    // fragment bases
    const u32 Abase = sbase + X_OFF + (u32)(((warp_m * 64 + gid) * STW72 + tid4 * 2) * 4);
    const u32 Bbase = sbase + W_OFF + (u32)(((warp_n * 32 + gid) * STW72 + tid4 * 2) * 4);

    // reader identity: row r, tree pair
    const int r    = tid & 127;
    const int jhi  = tid >> 7;             // 0/1 -> trees {0,1} or {2,3} of group
    const int sr   = (r >> 1) & 3;         // quad swizzle key for this row
    const u32 Rrow = sbase + L_OFF + (u32)(r * 20 * 16);

    float oc0 = 0.f, oc1 = 0.f;

    #pragma unroll 1
    for (int g = 0; g < NGROUP; g++) {
        cp_wait<0>();
        __syncthreads();             // W(g) (+X on g=0) visible; L(g-1) reads done

        // ================= GEMM(g): acc starts at 0.5*bias =================
        float acc[4][4][4];
        {
            const float* bsp = c_bs05 + ((g * 4 + warp_n) * 32 + tid4 * 2);
            #pragma unroll
            for (int nt = 0; nt < 4; nt++) {
                float b0 = bsp[nt * 8], b1 = bsp[nt * 8 + 1];
                #pragma unroll
                for (int mt = 0; mt < 4; mt++) {
                    acc[mt][nt][0] = b0; acc[mt][nt][1] = b1;
                    acc[mt][nt][2] = b0; acc[mt][nt][3] = b1;
                }
            }
        }

        #pragma unroll
        for (int kk = 0; kk < 8; kk++) {
            u32 a[4][4];
            #pragma unroll
            for (int mt = 0; mt < 4; mt++) {
                const u32 r0 = Abase + (u32)((mt * 16 * STW72 + kk * 8) * 4);
                lds_v2(a[mt][0], a[mt][2], r0);
                lds_v2(a[mt][1], a[mt][3], r0 + 8 * STW72 * 4);
            }
            #pragma unroll
            for (int nt = 0; nt < 4; nt++) {
                u32 b0, b1;
                lds_v2(b0, b1, Bbase + (u32)((nt * 8 * STW72 + kk * 8) * 4));
                #pragma unroll
                for (int mt = 0; mt < 4; mt++)
                    MMA_F16(acc[mt][nt], a[mt][0], a[mt][1], a[mt][2], a[mt][3], b0, b1);
            }
        }

        __syncthreads();             // W(g) reads complete -> buffer free

        // prefetch W(g+1) (overlaps logits store + epilogue)
        if (g < NGROUP - 1) {
            const __half* src = g_Wh + (size_t)(g + 1) * 128 * F;
            #pragma unroll
            for (int j = 0; j < 8; j++) {
                int i = tid + j * NTHREADS;
                int row = i >> 4, c = i & 15;
                cpa16(sbase + W_OFF + (u32)(row * STW72 * 4) + c * 16, src + row * F + c * 8);
            }
            CP_COMMIT();
        }

        // ---- pack fp16 half-logits, STS.128 (8 per thread, conflict-free) ----
        #pragma unroll
        for (int mt = 0; mt < 4; mt++) {
            #pragma unroll
            for (int half = 0; half < 2; half++) {
                const int row = warp_m * 64 + mt * 16 + half * 8 + gid;
                u32 h0 = pack_h2(acc[mt][0][2 * half], acc[mt][0][2 * half + 1]);
                u32 h1 = pack_h2(acc[mt][1][2 * half], acc[mt][1][2 * half + 1]);
                u32 h2 = pack_h2(acc[mt][2][2 * half], acc[mt][2][2 * half + 1]);
                u32 h3 = pack_h2(acc[mt][3][2 * half], acc[mt][3][2 * half + 1]);
                u32 quad = (u32)(row * 20 + warp_n * 4 + (tid4 ^ ((row >> 1) & 3)));
                sts_v4(sbase + L_OFF + quad * 16, h0, h1, h2, h3);
            }
        }
        __syncthreads();             // logits(g) visible

        // ---- epilogue: 2 (row, tree) tasks per thread ----
        #pragma unroll
        for (int j2 = 0; j2 < 2; j2++) {
            const int tp = jhi * 2 + j2;        // tree-in-group 0..3
            const int t  = g * 4 + tp;
            const float* lc = c_lc + t * 32;
            float s[32];
            #pragma unroll
            for (int q = 0; q < 4; q++) {       // logical quad = writer's tid4
                u32 w0, w1, w2, w3;
                lds_v4(w0, w1, w2, w3, Rrow + (u32)(tp * 4 + (q ^ sr)) * 16);
                const u32 ws[4] = {w0, w1, w2, w3};
                #pragma unroll
                for (int nt = 0; nt < 4; nt++) {
                    __half2 hv = *(__half2*)&ws[nt];
                    const int n = nt * 8 + 2 * q;
                    s[n]     = __low2float(hv);
                    s[n + 1] = __high2float(hv);
                }
            }
            // sigmoid: values are l/2 already -> s = 0.5*tanh + 0.5
            #pragma unroll
            for (int n = 0; n < NI; n++) {
                float th;
                asm("tanh.approx.f32 %0, %1;" : "=f"(th) : "f"(s[n]));
                s[n] = fmaf(0.5f, th, 0.5f);
            }
            float Pn[NI];
            Pn[0] = 1.f;
            #pragma unroll
            for (int i = 0; i < 15; i++) {
                float gg = s[i];
                float pr = Pn[i] * gg;
                Pn[2 * i + 2] = pr;
                Pn[2 * i + 1] = Pn[i] - pr;
            }
            float a0 = 0.f;
            #pragma unroll
            for (int l = 0; l < 16; l++) {      // leaf pair l, parent node 15+l
                const int p = 15 + l;
                float u = fmaf(s[p], lc[2 * l + 1], lc[2 * l]);
                a0 = fmaf(Pn[p], u, a0);
            }
            oc0 += a0;
            oc1 += c_wt[t] - a0;
        }
    }

    // ---- reduce 2 thread-partials per row (X region reused as scratch) ----
    __syncthreads();
    smf[r * 4 + jhi * 2 + 0] = oc0;
    smf[r * 4 + jhi * 2 + 1] = oc1;
    __syncthreads();
    if (tid < TILE_M) {
        float a0 = smf[tid * 4 + 0] + smf[tid * 4 + 2];
        float a1 = smf[tid * 4 + 1] + smf[tid * 4 + 3];
        int row = m0 + tid;
        if (row < B) ((float2*)out)[row] = make_float2(a0, a1);
    }
}

// ---------------- launch ----------------
extern "C" void kernel_launch(void* const* d_in, const int* in_sizes, int n_in,
                              void* d_out, int out_size)
{
    const float* x  = (const float*)d_in[0];  // [B, 128]
    const float* sw = (const float*)d_in[1];  // [T, 31, 128]
    const float* sb = (const float*)d_in[2];  // [T, 31]
    const float* ll = (const float*)d_in[3];  // [T, 32, 2]
    const float* tw = (const float*)d_in[4];  // [T]
    const float* fm = (const float*)d_in[5];  // [T, 128]

    int T = in_sizes[4];
    if (T > TMAX) T = TMAX;
    int B = in_sizes[0] / F;

    cudaFuncSetAttribute(forest_mma, cudaFuncAttributeMaxDynamicSharedMemorySize, SMEM_BYTES);

    prep<<<(NGROUP * 128 * F + 255) / 256, 256>>>(sw, fm, sb, ll, tw, T);

    // constants from device scratch (D2D async: graph-capturable)
    void* p = nullptr;
    cudaGetSymbolAddress(&p, g_bs);
    cudaMemcpyToSymbolAsync(c_bs05, p, (size_t)TMAX * 32 * sizeof(float), 0,
                            cudaMemcpyDeviceToDevice, 0);
    cudaGetSymbolAddress(&p, g_lc);
    cudaMemcpyToSymbolAsync(c_lc, p, (size_t)TMAX * 32 * sizeof(float), 0,
                            cudaMemcpyDeviceToDevice, 0);
    cudaGetSymbolAddress(&p, g_wt);
    cudaMemcpyToSymbolAsync(c_wt, p, (size_t)TMAX * sizeof(float), 0,
                            cudaMemcpyDeviceToDevice, 0);

    forest_mma<<<(B + TILE_M - 1) / TILE_M, NTHREADS, SMEM_BYTES>>>(x, (float*)d_out, B);
}